// round 1
// baseline (speedup 1.0000x reference)
#include <cuda_runtime.h>
#include <math.h>

#define BB 8
#define CC 16
#define HH 240
#define WW 320
#define NN (HH*WW)

// ---------------- device-global state (no allocations allowed) ----------------
__device__ float g_R[BB][9];
__device__ float g_t[BB][3];
__device__ float g_acc[BB][27];          // 21 upper-tri JtWJ + 6 Rhs
__device__ float g_jfx[BB*CC*NN];        // normalized sobel dx
__device__ float g_jfy[BB*CC*NN];        // normalized sobel dy

// ---------------- helpers ----------------
__device__ __forceinline__ void rodrigues(float wx, float wy, float wz, float* R) {
    float th = sqrtf(wx*wx + wy*wy + wz*wz) + 1e-12f;
    float inv = 1.0f / th;
    float ax = wx*inv, ay = wy*inv, az = wz*inv;
    float s = sinf(th), c = cosf(th), mc = 1.0f - c;
    R[0] = c + mc*ax*ax;     R[1] = mc*ax*ay - s*az;  R[2] = mc*ax*az + s*ay;
    R[3] = mc*ax*ay + s*az;  R[4] = c + mc*ay*ay;     R[5] = mc*ay*az - s*ax;
    R[6] = mc*ax*az - s*ay;  R[7] = mc*ay*az + s*ax;  R[8] = c + mc*az*az;
}

// ---------------- init: pose from twist, zero accumulators ----------------
__global__ void initKernel(const float* __restrict__ twist0) {
    int b = threadIdx.x;
    if (b >= BB) return;
    rodrigues(twist0[b*6+0], twist0[b*6+1], twist0[b*6+2], g_R[b]);
    g_t[b][0] = twist0[b*6+3];
    g_t[b][1] = twist0[b*6+4];
    g_t[b][2] = twist0[b*6+5];
#pragma unroll
    for (int k = 0; k < 27; k++) g_acc[b][k] = 0.0f;
}

// ---------------- sobel (normalized) precompute ----------------
__global__ void sobelKernel(const float* __restrict__ x0) {
    int idx = blockIdx.x * blockDim.x + threadIdx.x;
    if (idx >= BB*CC*NN) return;
    int p  = idx % NN;
    int bc = idx / NN;
    int v = p / WW, u = p - v*WW;
    const float* img = x0 + bc*NN;
    int um = max(u-1, 0), up = min(u+1, WW-1);
    int vm = max(v-1, 0), vp = min(v+1, HH-1);
    float tl = img[vm*WW+um], tc_ = img[vm*WW+u], tr = img[vm*WW+up];
    float ml = img[v *WW+um],                      mr = img[v *WW+up];
    float bl = img[vp*WW+um], bc_ = img[vp*WW+u], br = img[vp*WW+up];
    float dx = tr - tl + 2.0f*(mr - ml) + (br - bl);
    float dy = bl - tl + 2.0f*(bc_ - tc_) + (br - tr);
    float rinv = rsqrtf(dx*dx + dy*dy + 1e-8f);
    g_jfx[idx] = dx * rinv;
    g_jfy[idx] = dy * rinv;
}

// ---------------- per-iteration accumulation ----------------
__global__ __launch_bounds__(256)
void iterKernel(const float* __restrict__ x0, const float* __restrict__ x1,
                const float* __restrict__ invD0, const float* __restrict__ invD1,
                const float* __restrict__ sigma0, const float* __restrict__ sigma1,
                const float* __restrict__ Kmat)
{
    const int b = blockIdx.y;
    const int p = blockIdx.x * 256 + threadIdx.x;

    float acc[27];
#pragma unroll
    for (int k = 0; k < 27; k++) acc[k] = 0.0f;

    if (p < NN) {
        const float fx = Kmat[b*4+0], fy = Kmat[b*4+1];
        const float cx = Kmat[b*4+2], cy = Kmat[b*4+3];
        const float* Rb = g_R[b];
        const float* tb = g_t[b];

        int vpix = p / WW;
        int upix = p - vpix*WW;
        float x = ((float)upix - cx) / fx;
        float y = ((float)vpix - cy) / fy;
        float d = invD0[b*NN + p];

        float X = Rb[0]*x + Rb[1]*y + Rb[2] + tb[0]*d;
        float Y = Rb[3]*x + Rb[4]*y + Rb[5] + tb[1]*d;
        float S = Rb[6]*x + Rb[7]*y + Rb[8] + tb[2]*d;
        float invS = 1.0f / S;
        float u = X * invS * fx + cx;
        float v = Y * invS * fy + cy;
        float invz = d * invS;

        // bilinear setup (shared across channels)
        float uc = fminf(fmaxf(u, 0.0f), (float)(WW-1));
        float vc = fminf(fmaxf(v, 0.0f), (float)(HH-1));
        float x0f = floorf(uc), y0f = floorf(vc);
        float wx = uc - x0f, wy = vc - y0f;
        int xi0 = (int)x0f, yi0 = (int)y0f;
        int xi1 = min(xi0 + 1, WW-1), yi1 = min(yi0 + 1, HH-1);
        float w00 = (1.0f-wx)*(1.0f-wy), w01 = wx*(1.0f-wy);
        float w10 = (1.0f-wx)*wy,        w11 = wx*wy;
        int o00 = yi0*WW + xi0, o01 = yi0*WW + xi1;
        int o10 = yi1*WW + xi0, o11 = yi1*WW + xi1;

        // occlusion check
        const float* D1 = invD1 + b*NN;
        float dz = D1[o00]*w00 + D1[o01]*w01 + D1[o10]*w10 + D1[o11]*w11;
        bool inlier = invz > dz - 0.1f;
        bool inview = (u > 0.0f) && (u < (float)WW) && (v > 0.0f) && (v < (float)HH);

        if (inlier && inview) {
            float Saa = 0.0f, Sab = 0.0f, Sbb = 0.0f, Sar = 0.0f, Sbr = 0.0f;
            const int cbase = b*CC*NN + p;   // center arrays (stride NN per channel)
            const int gbase = b*CC*NN;       // gather arrays
#pragma unroll 4
            for (int c = 0; c < CC; c++) {
                int off = cbase + c*NN;
                float a  = g_jfx[off];
                float g  = g_jfy[off];
                float xc = x0[off];
                float s0 = sigma0[off];
                const float* X1 = x1     + gbase + c*NN;
                const float* S1 = sigma1 + gbase + c*NN;
                float fr = X1[o00]*w00 + X1[o01]*w01 + X1[o10]*w10 + X1[o11]*w11;
                float sr = S1[o00]*w00 + S1[o01]*w01 + S1[o10]*w10 + S1[o11]*w11;
                float s2  = sr*sr + s0*s0;
                float wgt = __fdividef(1.0f, s2);
                float res = fr - xc;
                float aw = a * wgt;
                float gw = g * wgt;
                Saa += aw * a;
                Sab += aw * g;
                Sbb += gw * g;
                Sar += aw * res;
                Sbr += gw * res;
            }

            // warp Jacobian (pixel-level)
            float Jx[6], Jy[6];
            float xy = x*y;
            Jx[0] = -xy*fx;        Jx[1] = (1.0f + x*x)*fx; Jx[2] = -y*fx;
            Jx[3] = d*fx;          Jx[4] = 0.0f;            Jx[5] = -d*x*fx;
            Jy[0] = -(1.0f+y*y)*fy; Jy[1] = xy*fy;          Jy[2] = x*fy;
            Jy[3] = 0.0f;          Jy[4] = d*fy;            Jy[5] = -d*y*fy;

            int idx = 0;
#pragma unroll
            for (int k = 0; k < 6; k++) {
#pragma unroll
                for (int l = k; l < 6; l++) {
                    acc[idx++] = Saa*Jx[k]*Jx[l] + Sab*(Jx[k]*Jy[l] + Jy[k]*Jx[l]) + Sbb*Jy[k]*Jy[l];
                }
            }
#pragma unroll
            for (int k = 0; k < 6; k++) acc[21+k] = Sar*Jx[k] + Sbr*Jy[k];
        }
    }

    // ---- block reduction of 27 values, then per-block atomicAdd ----
#pragma unroll
    for (int k = 0; k < 27; k++) {
#pragma unroll
        for (int off = 16; off > 0; off >>= 1)
            acc[k] += __shfl_down_sync(0xFFFFFFFFu, acc[k], off);
    }
    __shared__ float sm[27][8];
    int lane = threadIdx.x & 31;
    int warp = threadIdx.x >> 5;
    if (lane == 0) {
#pragma unroll
        for (int k = 0; k < 27; k++) sm[k][warp] = acc[k];
    }
    __syncthreads();
    if (threadIdx.x < 27) {
        float s = 0.0f;
#pragma unroll
        for (int w = 0; w < 8; w++) s += sm[threadIdx.x][w];
        atomicAdd(&g_acc[b][threadIdx.x], s);
    }
}

// ---------------- 6x6 LM solve + pose update ----------------
__global__ void solveKernel(float* __restrict__ out, int last) {
    int b = threadIdx.x;
    if (b >= BB) return;

    // reconstruct symmetric JtWJ + Rhs
    double Jt[6][6];
    int idx = 0;
#pragma unroll
    for (int k = 0; k < 6; k++)
#pragma unroll
        for (int l = k; l < 6; l++) {
            double vv = (double)g_acc[b][idx++];
            Jt[k][l] = vv; Jt[l][k] = vv;
        }
    double tr = 0.0;
    for (int k = 0; k < 6; k++) tr += Jt[k][k];
    double lam = tr * 1e-6;

    double M[6][7];
    for (int i = 0; i < 6; i++) {
        for (int j = 0; j < 6; j++) M[i][j] = Jt[i][j] + (i == j ? lam : 0.0);
        M[i][6] = (double)g_acc[b][21+i];
    }
    // Gaussian elimination with partial pivoting
    for (int k = 0; k < 6; k++) {
        int piv = k; double mx = fabs(M[k][k]);
        for (int i = k+1; i < 6; i++) {
            double a = fabs(M[i][k]);
            if (a > mx) { mx = a; piv = i; }
        }
        if (piv != k)
            for (int j = k; j < 7; j++) { double tmp = M[k][j]; M[k][j] = M[piv][j]; M[piv][j] = tmp; }
        double inv = 1.0 / M[k][k];
        for (int i = k+1; i < 6; i++) {
            double f = M[i][k] * inv;
            for (int j = k; j < 7; j++) M[i][j] -= f * M[k][j];
        }
    }
    double xi[6];
    for (int i = 5; i >= 0; i--) {
        double s = M[i][6];
        for (int j = i+1; j < 6; j++) s -= M[i][j] * xi[j];
        xi[i] = s / M[i][i];
    }

    // d_R = rodrigues(-xi[:3]); d_t = -(d_R @ xi[3:]); t += R@d_t; R = R@d_R
    float dR[9];
    rodrigues(-(float)xi[0], -(float)xi[1], -(float)xi[2], dR);
    float x3 = (float)xi[3], x4 = (float)xi[4], x5 = (float)xi[5];
    float dt[3];
    dt[0] = -(dR[0]*x3 + dR[1]*x4 + dR[2]*x5);
    dt[1] = -(dR[3]*x3 + dR[4]*x4 + dR[5]*x5);
    dt[2] = -(dR[6]*x3 + dR[7]*x4 + dR[8]*x5);

    float Rb[9], tb[3];
#pragma unroll
    for (int i = 0; i < 9; i++) Rb[i] = g_R[b][i];
#pragma unroll
    for (int i = 0; i < 3; i++) tb[i] = g_t[b][i];

    float nt[3], nR[9];
    for (int i = 0; i < 3; i++)
        nt[i] = Rb[i*3+0]*dt[0] + Rb[i*3+1]*dt[1] + Rb[i*3+2]*dt[2] + tb[i];
    for (int i = 0; i < 3; i++)
        for (int j = 0; j < 3; j++)
            nR[i*3+j] = Rb[i*3+0]*dR[0*3+j] + Rb[i*3+1]*dR[1*3+j] + Rb[i*3+2]*dR[2*3+j];

#pragma unroll
    for (int i = 0; i < 9; i++) g_R[b][i] = nR[i];
#pragma unroll
    for (int i = 0; i < 3; i++) g_t[b][i] = nt[i];
#pragma unroll
    for (int k = 0; k < 27; k++) g_acc[b][k] = 0.0f;   // ready for next iteration

    if (last) {
#pragma unroll
        for (int i = 0; i < 9; i++) out[b*12 + i] = nR[i];
#pragma unroll
        for (int i = 0; i < 3; i++) out[b*12 + 9 + i] = nt[i];
    }
}

// ---------------- launch ----------------
extern "C" void kernel_launch(void* const* d_in, const int* in_sizes, int n_in,
                              void* d_out, int out_size) {
    const float* twist0 = (const float*)d_in[0];
    const float* x0     = (const float*)d_in[1];
    const float* x1     = (const float*)d_in[2];
    const float* invD0  = (const float*)d_in[3];
    const float* invD1  = (const float*)d_in[4];
    const float* sigma0 = (const float*)d_in[5];
    const float* sigma1 = (const float*)d_in[6];
    const float* Kmat   = (const float*)d_in[7];
    float* out = (float*)d_out;

    initKernel<<<1, BB>>>(twist0);
    sobelKernel<<<(BB*CC*NN + 255)/256, 256>>>(x0);
    for (int it = 0; it < 3; ++it) {
        dim3 grid(NN/256, BB);
        iterKernel<<<grid, 256>>>(x0, x1, invD0, invD1, sigma0, sigma1, Kmat);
        solveKernel<<<1, BB>>>(out, it == 2);
    }
}

// round 2
// speedup vs baseline: 1.0231x; 1.0231x over previous
#include <cuda_runtime.h>
#include <math.h>

#define BB 8
#define CC 16
#define HH 240
#define WW 320
#define NN (HH*WW)
#define BCN (BB*CC*NN)

// ---------------- device-global state (no allocations allowed) ----------------
__device__ float g_R[BB][9];
__device__ float g_t[BB][3];
__device__ float g_acc[BB][27];          // 21 upper-tri JtWJ + 6 Rhs
__device__ float g_jf2[BCN*2];           // interleaved (jfx, jfy)
__device__ float g_x1s1[BCN*2];          // interleaved (x1, sigma1)

// ---------------- helpers ----------------
__device__ __forceinline__ void rodrigues(float wx, float wy, float wz, float* R) {
    float th = sqrtf(wx*wx + wy*wy + wz*wz) + 1e-12f;
    float inv = 1.0f / th;
    float ax = wx*inv, ay = wy*inv, az = wz*inv;
    float s = sinf(th), c = cosf(th), mc = 1.0f - c;
    R[0] = c + mc*ax*ax;     R[1] = mc*ax*ay - s*az;  R[2] = mc*ax*az + s*ay;
    R[3] = mc*ax*ay + s*az;  R[4] = c + mc*ay*ay;     R[5] = mc*ay*az - s*ax;
    R[6] = mc*ax*az - s*ay;  R[7] = mc*ay*az + s*ax;  R[8] = c + mc*az*az;
}

// ---------------- init: pose from twist, zero accumulators ----------------
__global__ void initKernel(const float* __restrict__ twist0) {
    int b = threadIdx.x;
    if (b >= BB) return;
    rodrigues(twist0[b*6+0], twist0[b*6+1], twist0[b*6+2], g_R[b]);
    g_t[b][0] = twist0[b*6+3];
    g_t[b][1] = twist0[b*6+4];
    g_t[b][2] = twist0[b*6+5];
#pragma unroll
    for (int k = 0; k < 27; k++) g_acc[b][k] = 0.0f;
}

// ---------------- pack: normalized sobel (float2) + interleaved x1/sigma1 ----------------
__global__ __launch_bounds__(256)
void packKernel(const float* __restrict__ x0, const float* __restrict__ x1,
                const float* __restrict__ sigma1) {
    int t = blockIdx.x * 256 + threadIdx.x;     // one thread = 4 horizontal pixels
    int idx4 = t * 4;
    if (idx4 >= BCN) return;
    int bc = idx4 / NN;
    int p4 = idx4 - bc*NN;
    int v  = p4 / WW;
    int u0 = p4 - v*WW;                          // u0 % 4 == 0, row-contained

    const float* img = x0 + bc*NN;
    int vm = max(v-1, 0)*WW, v0 = v*WW, vp = min(v+1, HH-1)*WW;
    int ul = max(u0-1, 0);
    int ur = min(u0+4, WW-1);

    // 6-wide column windows for 3 rows
    float top[6], mid[6], bot[6];
    {
        float4 c;
        c = *(const float4*)(img + vm + u0);
        top[0]=img[vm+ul]; top[1]=c.x; top[2]=c.y; top[3]=c.z; top[4]=c.w; top[5]=img[vm+ur];
        c = *(const float4*)(img + v0 + u0);
        mid[0]=img[v0+ul]; mid[1]=c.x; mid[2]=c.y; mid[3]=c.z; mid[4]=c.w; mid[5]=img[v0+ur];
        c = *(const float4*)(img + vp + u0);
        bot[0]=img[vp+ul]; bot[1]=c.x; bot[2]=c.y; bot[3]=c.z; bot[4]=c.w; bot[5]=img[vp+ur];
    }

    float ag[8];
#pragma unroll
    for (int i = 0; i < 4; i++) {
        float tl = top[i], tc_ = top[i+1], tr = top[i+2];
        float ml = mid[i],                 mr = mid[i+2];
        float bl = bot[i], bc_ = bot[i+1], br = bot[i+2];
        float dx = tr - tl + 2.0f*(mr - ml) + (br - bl);
        float dy = bl - tl + 2.0f*(bc_ - tc_) + (br - tr);
        float rinv = rsqrtf(dx*dx + dy*dy + 1e-8f);
        ag[i*2+0] = dx * rinv;
        ag[i*2+1] = dy * rinv;
    }
    float4* jf = (float4*)(g_jf2 + (size_t)idx4*2);
    jf[0] = make_float4(ag[0], ag[1], ag[2], ag[3]);
    jf[1] = make_float4(ag[4], ag[5], ag[6], ag[7]);

    float4 xv = *(const float4*)(x1 + idx4);
    float4 sv = *(const float4*)(sigma1 + idx4);
    float4* xs = (float4*)(g_x1s1 + (size_t)idx4*2);
    xs[0] = make_float4(xv.x, sv.x, xv.y, sv.y);
    xs[1] = make_float4(xv.z, sv.z, xv.w, sv.w);
}

// ---------------- per-iteration accumulation (4 pixels / thread) ----------------
__global__ __launch_bounds__(256)
void iterKernel(const float* __restrict__ x0, const float* __restrict__ invD0,
                const float* __restrict__ invD1, const float* __restrict__ sigma0,
                const float* __restrict__ Kmat)
{
    const int b  = blockIdx.y;
    const int p4 = (blockIdx.x * 256 + threadIdx.x) * 4;

    float acc[27];
#pragma unroll
    for (int k = 0; k < 27; k++) acc[k] = 0.0f;

    {
        const float fx = Kmat[b*4+0], fy = Kmat[b*4+1];
        const float cx = Kmat[b*4+2], cy = Kmat[b*4+3];
        const float ifx = 1.0f/fx, ify = 1.0f/fy;
        const float* Rb = g_R[b];
        const float* tb = g_t[b];

        int vpix = p4 / WW;
        int u0   = p4 - vpix*WW;
        float y  = ((float)vpix - cy) * ify;
        float4 d4 = *(const float4*)(invD0 + b*NN + p4);
        float dd[4] = {d4.x, d4.y, d4.z, d4.w};

        // per-pixel warp state
        float xs_[4], valid[4];
        float w00[4], w01[4], w10[4], w11[4];
        int   o00[4], o01[4], o10[4], o11[4];
        const float* D1 = invD1 + b*NN;

#pragma unroll
        for (int i = 0; i < 4; i++) {
            float x = ((float)(u0 + i) - cx) * ifx;
            xs_[i] = x;
            float d = dd[i];
            float X = Rb[0]*x + Rb[1]*y + Rb[2] + tb[0]*d;
            float Y = Rb[3]*x + Rb[4]*y + Rb[5] + tb[1]*d;
            float S = Rb[6]*x + Rb[7]*y + Rb[8] + tb[2]*d;
            float invS = __fdividef(1.0f, S);
            float u = X * invS * fx + cx;
            float v = Y * invS * fy + cy;
            float invz = d * invS;

            float uc = fminf(fmaxf(u, 0.0f), (float)(WW-1));
            float vc = fminf(fmaxf(v, 0.0f), (float)(HH-1));
            float x0f = floorf(uc), y0f = floorf(vc);
            float wx = uc - x0f, wy = vc - y0f;
            int xi0 = (int)x0f, yi0 = (int)y0f;
            int xi1 = min(xi0 + 1, WW-1), yi1 = min(yi0 + 1, HH-1);
            w00[i] = (1.0f-wx)*(1.0f-wy); w01[i] = wx*(1.0f-wy);
            w10[i] = (1.0f-wx)*wy;        w11[i] = wx*wy;
            o00[i] = yi0*WW + xi0; o01[i] = yi0*WW + xi1;
            o10[i] = yi1*WW + xi0; o11[i] = yi1*WW + xi1;

            float dz = D1[o00[i]]*w00[i] + D1[o01[i]]*w01[i]
                     + D1[o10[i]]*w10[i] + D1[o11[i]]*w11[i];
            bool inlier = invz > dz - 0.1f;
            bool inview = (u > 0.0f) && (u < (float)WW) && (v > 0.0f) && (v < (float)HH);
            valid[i] = (inlier && inview) ? 1.0f : 0.0f;
        }

        // channel loop: accumulate 5 sums per pixel
        float Saa[4] = {0,0,0,0}, Sab[4] = {0,0,0,0}, Sbb[4] = {0,0,0,0};
        float Sar[4] = {0,0,0,0}, Sbr[4] = {0,0,0,0};
        const int cbase = b*CC*NN + p4;
#pragma unroll 2
        for (int c = 0; c < CC; c++) {
            int base = cbase + c*NN;
            const float4* jf = (const float4*)(g_jf2 + (size_t)base*2);
            float4 jfA = jf[0], jfB = jf[1];
            float a_[4] = {jfA.x, jfA.z, jfB.x, jfB.z};
            float g_[4] = {jfA.y, jfA.w, jfB.y, jfB.w};
            float4 x0v = *(const float4*)(x0 + base);
            float4 s0v = *(const float4*)(sigma0 + base);
            float xc[4] = {x0v.x, x0v.y, x0v.z, x0v.w};
            float s0[4] = {s0v.x, s0v.y, s0v.z, s0v.w};
            const float* XS = g_x1s1 + (size_t)(base - p4)*2;  // (b,c) plane base
#pragma unroll
            for (int i = 0; i < 4; i++) {
                float2 f00 = *(const float2*)(XS + o00[i]*2);
                float2 f01 = *(const float2*)(XS + o01[i]*2);
                float2 f10 = *(const float2*)(XS + o10[i]*2);
                float2 f11 = *(const float2*)(XS + o11[i]*2);
                float fr = f00.x*w00[i] + f01.x*w01[i] + f10.x*w10[i] + f11.x*w11[i];
                float sr = f00.y*w00[i] + f01.y*w01[i] + f10.y*w10[i] + f11.y*w11[i];
                float s2 = sr*sr + s0[i]*s0[i];
                float wgt = __fdividef(1.0f, s2);
                float res = fr - xc[i];
                float aw = a_[i]*wgt, gw = g_[i]*wgt;
                Saa[i] += aw*a_[i];
                Sab[i] += aw*g_[i];
                Sbb[i] += gw*g_[i];
                Sar[i] += aw*res;
                Sbr[i] += gw*res;
            }
        }

        // expand each pixel's S into 27 accumulators
#pragma unroll
        for (int i = 0; i < 4; i++) {
            float vmask = valid[i];
            float saa = Saa[i]*vmask, sab = Sab[i]*vmask, sbb = Sbb[i]*vmask;
            float sar = Sar[i]*vmask, sbr = Sbr[i]*vmask;
            float x = xs_[i], d = dd[i];
            float xy = x*y;
            float Jx[6], Jy[6];
            Jx[0] = -xy*fx;          Jx[1] = (1.0f + x*x)*fx; Jx[2] = -y*fx;
            Jx[3] = d*fx;            Jx[4] = 0.0f;            Jx[5] = -d*x*fx;
            Jy[0] = -(1.0f+y*y)*fy;  Jy[1] = xy*fy;           Jy[2] = x*fy;
            Jy[3] = 0.0f;            Jy[4] = d*fy;            Jy[5] = -d*y*fy;
            int idx = 0;
#pragma unroll
            for (int k = 0; k < 6; k++) {
#pragma unroll
                for (int l = k; l < 6; l++) {
                    acc[idx++] += saa*Jx[k]*Jx[l] + sab*(Jx[k]*Jy[l] + Jy[k]*Jx[l]) + sbb*Jy[k]*Jy[l];
                }
            }
#pragma unroll
            for (int k = 0; k < 6; k++) acc[21+k] += sar*Jx[k] + sbr*Jy[k];
        }
    }

    // ---- block reduction of 27 values, then per-block atomicAdd ----
#pragma unroll
    for (int k = 0; k < 27; k++) {
#pragma unroll
        for (int off = 16; off > 0; off >>= 1)
            acc[k] += __shfl_down_sync(0xFFFFFFFFu, acc[k], off);
    }
    __shared__ float sm[27][8];
    int lane = threadIdx.x & 31;
    int warp = threadIdx.x >> 5;
    if (lane == 0) {
#pragma unroll
        for (int k = 0; k < 27; k++) sm[k][warp] = acc[k];
    }
    __syncthreads();
    if (threadIdx.x < 27) {
        float s = 0.0f;
#pragma unroll
        for (int w = 0; w < 8; w++) s += sm[threadIdx.x][w];
        atomicAdd(&g_acc[blockIdx.y][threadIdx.x], s);
    }
}

// ---------------- 6x6 LM solve (fp32) + pose update ----------------
__global__ void solveKernel(float* __restrict__ out, int last) {
    int b = threadIdx.x;
    if (b >= BB) return;

    float M[6][7];
    {
        float Jt[6][6];
        int idx = 0;
#pragma unroll
        for (int k = 0; k < 6; k++)
#pragma unroll
            for (int l = k; l < 6; l++) {
                float vv = g_acc[b][idx++];
                Jt[k][l] = vv; Jt[l][k] = vv;
            }
        float tr = 0.0f;
#pragma unroll
        for (int k = 0; k < 6; k++) tr += Jt[k][k];
        float lam = tr * 1e-6f;
#pragma unroll
        for (int i = 0; i < 6; i++) {
#pragma unroll
            for (int j = 0; j < 6; j++) M[i][j] = Jt[i][j] + (i == j ? lam : 0.0f);
            M[i][6] = g_acc[b][21+i];
        }
    }
    // Gaussian elimination with partial pivoting (fp32)
    for (int k = 0; k < 6; k++) {
        int piv = k; float mx = fabsf(M[k][k]);
        for (int i = k+1; i < 6; i++) {
            float a = fabsf(M[i][k]);
            if (a > mx) { mx = a; piv = i; }
        }
        if (piv != k)
            for (int j = k; j < 7; j++) { float tmp = M[k][j]; M[k][j] = M[piv][j]; M[piv][j] = tmp; }
        float inv = 1.0f / M[k][k];
        for (int i = k+1; i < 6; i++) {
            float f = M[i][k] * inv;
            for (int j = k; j < 7; j++) M[i][j] -= f * M[k][j];
        }
    }
    float xi[6];
    for (int i = 5; i >= 0; i--) {
        float s = M[i][6];
        for (int j = i+1; j < 6; j++) s -= M[i][j] * xi[j];
        xi[i] = s / M[i][i];
    }

    // d_R = rodrigues(-xi[:3]); d_t = -(d_R @ xi[3:]); t = R@d_t + t; R = R@d_R
    float dR[9];
    rodrigues(-xi[0], -xi[1], -xi[2], dR);
    float dt[3];
    dt[0] = -(dR[0]*xi[3] + dR[1]*xi[4] + dR[2]*xi[5]);
    dt[1] = -(dR[3]*xi[3] + dR[4]*xi[4] + dR[5]*xi[5]);
    dt[2] = -(dR[6]*xi[3] + dR[7]*xi[4] + dR[8]*xi[5]);

    float Rb[9], tb[3];
#pragma unroll
    for (int i = 0; i < 9; i++) Rb[i] = g_R[b][i];
#pragma unroll
    for (int i = 0; i < 3; i++) tb[i] = g_t[b][i];

    float nt[3], nR[9];
#pragma unroll
    for (int i = 0; i < 3; i++)
        nt[i] = Rb[i*3+0]*dt[0] + Rb[i*3+1]*dt[1] + Rb[i*3+2]*dt[2] + tb[i];
#pragma unroll
    for (int i = 0; i < 3; i++)
#pragma unroll
        for (int j = 0; j < 3; j++)
            nR[i*3+j] = Rb[i*3+0]*dR[0*3+j] + Rb[i*3+1]*dR[1*3+j] + Rb[i*3+2]*dR[2*3+j];

#pragma unroll
    for (int i = 0; i < 9; i++) g_R[b][i] = nR[i];
#pragma unroll
    for (int i = 0; i < 3; i++) g_t[b][i] = nt[i];
#pragma unroll
    for (int k = 0; k < 27; k++) g_acc[b][k] = 0.0f;   // ready for next iteration

    if (last) {
#pragma unroll
        for (int i = 0; i < 9; i++) out[b*12 + i] = nR[i];
#pragma unroll
        for (int i = 0; i < 3; i++) out[b*12 + 9 + i] = nt[i];
    }
}

// ---------------- launch ----------------
extern "C" void kernel_launch(void* const* d_in, const int* in_sizes, int n_in,
                              void* d_out, int out_size) {
    const float* twist0 = (const float*)d_in[0];
    const float* x0     = (const float*)d_in[1];
    const float* x1     = (const float*)d_in[2];
    const float* invD0  = (const float*)d_in[3];
    const float* invD1  = (const float*)d_in[4];
    const float* sigma0 = (const float*)d_in[5];
    const float* sigma1 = (const float*)d_in[6];
    const float* Kmat   = (const float*)d_in[7];
    float* out = (float*)d_out;

    initKernel<<<1, BB>>>(twist0);
    packKernel<<<BCN/4/256, 256>>>(x0, x1, sigma1);
    for (int it = 0; it < 3; ++it) {
        dim3 grid(NN/4/256, BB);
        iterKernel<<<grid, 256>>>(x0, invD0, invD1, sigma0, Kmat);
        solveKernel<<<1, BB>>>(out, it == 2);
    }
}

// round 3
// speedup vs baseline: 2.1331x; 2.0849x over previous
#include <cuda_runtime.h>
#include <cuda_fp16.h>
#include <math.h>

#define BB 8
#define CC 16
#define HH 240
#define WW 320
#define NN (HH*WW)
#define BCN (BB*CC*NN)

// ---------------- device-global state (no allocations allowed) ----------------
__device__ float g_R[BB][9];
__device__ float g_t[BB][3];
__device__ float g_acc[BB][27];          // 21 upper-tri JtWJ + 6 Rhs
__device__ uint2 g_cen[BCN];             // per (c,p): half2(a,g), half2(x0, sigma0^2)
__device__ __half2 g_gath[BCN];          // per (c,p): half2(x1, sigma1)

// ---------------- helpers ----------------
__device__ __forceinline__ void rodrigues(float wx, float wy, float wz, float* R) {
    float th = sqrtf(wx*wx + wy*wy + wz*wz) + 1e-12f;
    float inv = 1.0f / th;
    float ax = wx*inv, ay = wy*inv, az = wz*inv;
    float s = sinf(th), c = cosf(th), mc = 1.0f - c;
    R[0] = c + mc*ax*ax;     R[1] = mc*ax*ay - s*az;  R[2] = mc*ax*az + s*ay;
    R[3] = mc*ax*ay + s*az;  R[4] = c + mc*ay*ay;     R[5] = mc*ay*az - s*ax;
    R[6] = mc*ax*az - s*ay;  R[7] = mc*ay*az + s*ax;  R[8] = c + mc*az*az;
}

// ---------------- init: pose from twist, zero accumulators ----------------
__global__ void initKernel(const float* __restrict__ twist0) {
    int b = threadIdx.x;
    if (b >= BB) return;
    rodrigues(twist0[b*6+0], twist0[b*6+1], twist0[b*6+2], g_R[b]);
    g_t[b][0] = twist0[b*6+3];
    g_t[b][1] = twist0[b*6+4];
    g_t[b][2] = twist0[b*6+5];
#pragma unroll
    for (int k = 0; k < 27; k++) g_acc[b][k] = 0.0f;
}

// ---------------- pack: sobel + fp16 packing of all per-channel streams ----------------
__global__ __launch_bounds__(256)
void packKernel(const float* __restrict__ x0, const float* __restrict__ sigma0,
                const float* __restrict__ x1, const float* __restrict__ sigma1) {
    int t = blockIdx.x * 256 + threadIdx.x;     // one thread = 4 horizontal pixels
    int idx4 = t * 4;
    if (idx4 >= BCN) return;
    int bc = idx4 / NN;
    int p4 = idx4 - bc*NN;
    int v  = p4 / WW;
    int u0 = p4 - v*WW;                          // u0 % 4 == 0, row-contained

    const float* img = x0 + (size_t)bc*NN;
    int vm = max(v-1, 0)*WW, v0 = v*WW, vp = min(v+1, HH-1)*WW;
    int ul = max(u0-1, 0);
    int ur = min(u0+4, WW-1);

    float top[6], mid[6], bot[6];
    {
        float4 c;
        c = *(const float4*)(img + vm + u0);
        top[0]=img[vm+ul]; top[1]=c.x; top[2]=c.y; top[3]=c.z; top[4]=c.w; top[5]=img[vm+ur];
        c = *(const float4*)(img + v0 + u0);
        mid[0]=img[v0+ul]; mid[1]=c.x; mid[2]=c.y; mid[3]=c.z; mid[4]=c.w; mid[5]=img[v0+ur];
        c = *(const float4*)(img + vp + u0);
        bot[0]=img[vp+ul]; bot[1]=c.x; bot[2]=c.y; bot[3]=c.z; bot[4]=c.w; bot[5]=img[vp+ur];
    }

    float4 s0v = *(const float4*)(sigma0 + idx4);
    float s0a[4] = {s0v.x, s0v.y, s0v.z, s0v.w};

    uint2 cen[4];
#pragma unroll
    for (int i = 0; i < 4; i++) {
        float tl = top[i], tc_ = top[i+1], tr = top[i+2];
        float ml = mid[i],                 mr = mid[i+2];
        float bl = bot[i], bc_ = bot[i+1], br = bot[i+2];
        float dx = tr - tl + 2.0f*(mr - ml) + (br - bl);
        float dy = bl - tl + 2.0f*(bc_ - tc_) + (br - tr);
        float rinv = rsqrtf(dx*dx + dy*dy + 1e-8f);
        __half2 ag = __floats2half2_rn(dx*rinv, dy*rinv);
        __half2 xs = __floats2half2_rn(mid[i+1], s0a[i]*s0a[i]);
        cen[i].x = *(unsigned int*)&ag;
        cen[i].y = *(unsigned int*)&xs;
    }
    *(uint4*)&g_cen[idx4]   = make_uint4(cen[0].x, cen[0].y, cen[1].x, cen[1].y);
    *(uint4*)&g_cen[idx4+2] = make_uint4(cen[2].x, cen[2].y, cen[3].x, cen[3].y);

    float4 xv = *(const float4*)(x1 + idx4);
    float4 sv = *(const float4*)(sigma1 + idx4);
    __half2 h0 = __floats2half2_rn(xv.x, sv.x);
    __half2 h1 = __floats2half2_rn(xv.y, sv.y);
    __half2 h2 = __floats2half2_rn(xv.z, sv.z);
    __half2 h3 = __floats2half2_rn(xv.w, sv.w);
    *(uint4*)&g_gath[idx4] = make_uint4(*(unsigned int*)&h0, *(unsigned int*)&h1,
                                        *(unsigned int*)&h2, *(unsigned int*)&h3);
}

// ---------------- per-iteration accumulation (2 pixels / thread) ----------------
__global__ __launch_bounds__(256)
void iterKernel(const float* __restrict__ invD0, const float* __restrict__ invD1,
                const float* __restrict__ Kmat)
{
    const int b  = blockIdx.y;
    const int p2 = (blockIdx.x * 256 + threadIdx.x) * 2;

    float acc[27];
#pragma unroll
    for (int k = 0; k < 27; k++) acc[k] = 0.0f;

    {
        const float fx = Kmat[b*4+0], fy = Kmat[b*4+1];
        const float cx = Kmat[b*4+2], cy = Kmat[b*4+3];
        const float ifx = 1.0f/fx, ify = 1.0f/fy;
        const float* Rb = g_R[b];
        const float* tb = g_t[b];

        int vpix = p2 / WW;
        int u0   = p2 - vpix*WW;
        float y  = ((float)vpix - cy) * ify;
        float2 d2 = *(const float2*)(invD0 + (size_t)b*NN + p2);
        float dd[2] = {d2.x, d2.y};

        float xs_[2], valid[2];
        __half2 w00h[2], w01h[2], w10h[2], w11h[2];
        int o00[2], o01[2], o10[2], o11[2];
        const float* D1 = invD1 + (size_t)b*NN;

#pragma unroll
        for (int i = 0; i < 2; i++) {
            float x = ((float)(u0 + i) - cx) * ifx;
            xs_[i] = x;
            float d = dd[i];
            float X = Rb[0]*x + Rb[1]*y + Rb[2] + tb[0]*d;
            float Y = Rb[3]*x + Rb[4]*y + Rb[5] + tb[1]*d;
            float S = Rb[6]*x + Rb[7]*y + Rb[8] + tb[2]*d;
            float invS = __fdividef(1.0f, S);
            float u = X * invS * fx + cx;
            float v = Y * invS * fy + cy;
            float invz = d * invS;

            float uc = fminf(fmaxf(u, 0.0f), (float)(WW-1));
            float vc = fminf(fmaxf(v, 0.0f), (float)(HH-1));
            float x0f = floorf(uc), y0f = floorf(vc);
            float wx = uc - x0f, wy = vc - y0f;
            int xi0 = (int)x0f, yi0 = (int)y0f;
            int xi1 = min(xi0 + 1, WW-1), yi1 = min(yi0 + 1, HH-1);
            float w00 = (1.0f-wx)*(1.0f-wy), w01 = wx*(1.0f-wy);
            float w10 = (1.0f-wx)*wy,        w11 = wx*wy;
            o00[i] = yi0*WW + xi0; o01[i] = yi0*WW + xi1;
            o10[i] = yi1*WW + xi0; o11[i] = yi1*WW + xi1;
            w00h[i] = __float2half2_rn(w00); w01h[i] = __float2half2_rn(w01);
            w10h[i] = __float2half2_rn(w10); w11h[i] = __float2half2_rn(w11);

            float dz = D1[o00[i]]*w00 + D1[o01[i]]*w01 + D1[o10[i]]*w10 + D1[o11[i]]*w11;
            bool inlier = invz > dz - 0.1f;
            bool inview = (u > 0.0f) && (u < (float)WW) && (v > 0.0f) && (v < (float)HH);
            valid[i] = (inlier && inview) ? 1.0f : 0.0f;
        }

        float Saa[2] = {0,0}, Sab[2] = {0,0}, Sbb[2] = {0,0};
        float Sar[2] = {0,0}, Sbr[2] = {0,0};
        const size_t cbase = (size_t)b*CC*NN + p2;
#pragma unroll 4
        for (int c = 0; c < CC; c++) {
            size_t base = cbase + (size_t)c*NN;
            uint4 cv = __ldg((const uint4*)&g_cen[base]);
            const __half2* G = g_gath + (base - p2);   // (b,c) plane base
            unsigned int agu[2] = {cv.x, cv.z};
            unsigned int xsu[2] = {cv.y, cv.w};
#pragma unroll
            for (int i = 0; i < 2; i++) {
                __half2 h00 = __ldg(G + o00[i]);
                __half2 h01 = __ldg(G + o01[i]);
                __half2 h10 = __ldg(G + o10[i]);
                __half2 h11 = __ldg(G + o11[i]);
                __half2 fs = __hmul2(h00, w00h[i]);
                fs = __hfma2(h01, w01h[i], fs);
                fs = __hfma2(h10, w10h[i], fs);
                fs = __hfma2(h11, w11h[i], fs);
                float2 frsr = __half22float2(fs);
                float2 ag   = __half22float2(*(__half2*)&agu[i]);
                float2 xss  = __half22float2(*(__half2*)&xsu[i]);
                float s2  = frsr.y*frsr.y + xss.y;
                float wgt = __fdividef(1.0f, s2);
                float res = frsr.x - xss.x;
                float aw = ag.x*wgt, gw = ag.y*wgt;
                Saa[i] += aw*ag.x;
                Sab[i] += aw*ag.y;
                Sbb[i] += gw*ag.y;
                Sar[i] += aw*res;
                Sbr[i] += gw*res;
            }
        }

        // expand each pixel's S into 27 accumulators
#pragma unroll
        for (int i = 0; i < 2; i++) {
            float vmask = valid[i];
            float saa = Saa[i]*vmask, sab = Sab[i]*vmask, sbb = Sbb[i]*vmask;
            float sar = Sar[i]*vmask, sbr = Sbr[i]*vmask;
            float x = xs_[i], d = dd[i];
            float xy = x*y;
            float Jx[6], Jy[6];
            Jx[0] = -xy*fx;          Jx[1] = (1.0f + x*x)*fx; Jx[2] = -y*fx;
            Jx[3] = d*fx;            Jx[4] = 0.0f;            Jx[5] = -d*x*fx;
            Jy[0] = -(1.0f+y*y)*fy;  Jy[1] = xy*fy;           Jy[2] = x*fy;
            Jy[3] = 0.0f;            Jy[4] = d*fy;            Jy[5] = -d*y*fy;
            int idx = 0;
#pragma unroll
            for (int k = 0; k < 6; k++) {
#pragma unroll
                for (int l = k; l < 6; l++) {
                    acc[idx++] += saa*Jx[k]*Jx[l] + sab*(Jx[k]*Jy[l] + Jy[k]*Jx[l]) + sbb*Jy[k]*Jy[l];
                }
            }
#pragma unroll
            for (int k = 0; k < 6; k++) acc[21+k] += sar*Jx[k] + sbr*Jy[k];
        }
    }

    // ---- block reduction of 27 values, then per-block atomicAdd ----
#pragma unroll
    for (int k = 0; k < 27; k++) {
#pragma unroll
        for (int off = 16; off > 0; off >>= 1)
            acc[k] += __shfl_down_sync(0xFFFFFFFFu, acc[k], off);
    }
    __shared__ float sm[27][8];
    int lane = threadIdx.x & 31;
    int warp = threadIdx.x >> 5;
    if (lane == 0) {
#pragma unroll
        for (int k = 0; k < 27; k++) sm[k][warp] = acc[k];
    }
    __syncthreads();
    if (threadIdx.x < 27) {
        float s = 0.0f;
#pragma unroll
        for (int w = 0; w < 8; w++) s += sm[threadIdx.x][w];
        atomicAdd(&g_acc[blockIdx.y][threadIdx.x], s);
    }
}

// ---------------- 6x6 LM solve (fp32) + pose update ----------------
__global__ void solveKernel(float* __restrict__ out, int last) {
    int b = threadIdx.x;
    if (b >= BB) return;

    float M[6][7];
    {
        float Jt[6][6];
        int idx = 0;
#pragma unroll
        for (int k = 0; k < 6; k++)
#pragma unroll
            for (int l = k; l < 6; l++) {
                float vv = g_acc[b][idx++];
                Jt[k][l] = vv; Jt[l][k] = vv;
            }
        float tr = 0.0f;
#pragma unroll
        for (int k = 0; k < 6; k++) tr += Jt[k][k];
        float lam = tr * 1e-6f;
#pragma unroll
        for (int i = 0; i < 6; i++) {
#pragma unroll
            for (int j = 0; j < 6; j++) M[i][j] = Jt[i][j] + (i == j ? lam : 0.0f);
            M[i][6] = g_acc[b][21+i];
        }
    }
    for (int k = 0; k < 6; k++) {
        int piv = k; float mx = fabsf(M[k][k]);
        for (int i = k+1; i < 6; i++) {
            float a = fabsf(M[i][k]);
            if (a > mx) { mx = a; piv = i; }
        }
        if (piv != k)
            for (int j = k; j < 7; j++) { float tmp = M[k][j]; M[k][j] = M[piv][j]; M[piv][j] = tmp; }
        float inv = 1.0f / M[k][k];
        for (int i = k+1; i < 6; i++) {
            float f = M[i][k] * inv;
            for (int j = k; j < 7; j++) M[i][j] -= f * M[k][j];
        }
    }
    float xi[6];
    for (int i = 5; i >= 0; i--) {
        float s = M[i][6];
        for (int j = i+1; j < 6; j++) s -= M[i][j] * xi[j];
        xi[i] = s / M[i][i];
    }

    float dR[9];
    rodrigues(-xi[0], -xi[1], -xi[2], dR);
    float dt[3];
    dt[0] = -(dR[0]*xi[3] + dR[1]*xi[4] + dR[2]*xi[5]);
    dt[1] = -(dR[3]*xi[3] + dR[4]*xi[4] + dR[5]*xi[5]);
    dt[2] = -(dR[6]*xi[3] + dR[7]*xi[4] + dR[8]*xi[5]);

    float Rb[9], tb[3];
#pragma unroll
    for (int i = 0; i < 9; i++) Rb[i] = g_R[b][i];
#pragma unroll
    for (int i = 0; i < 3; i++) tb[i] = g_t[b][i];

    float nt[3], nR[9];
#pragma unroll
    for (int i = 0; i < 3; i++)
        nt[i] = Rb[i*3+0]*dt[0] + Rb[i*3+1]*dt[1] + Rb[i*3+2]*dt[2] + tb[i];
#pragma unroll
    for (int i = 0; i < 3; i++)
#pragma unroll
        for (int j = 0; j < 3; j++)
            nR[i*3+j] = Rb[i*3+0]*dR[0*3+j] + Rb[i*3+1]*dR[1*3+j] + Rb[i*3+2]*dR[2*3+j];

#pragma unroll
    for (int i = 0; i < 9; i++) g_R[b][i] = nR[i];
#pragma unroll
    for (int i = 0; i < 3; i++) g_t[b][i] = nt[i];
#pragma unroll
    for (int k = 0; k < 27; k++) g_acc[b][k] = 0.0f;

    if (last) {
#pragma unroll
        for (int i = 0; i < 9; i++) out[b*12 + i] = nR[i];
#pragma unroll
        for (int i = 0; i < 3; i++) out[b*12 + 9 + i] = nt[i];
    }
}

// ---------------- launch ----------------
extern "C" void kernel_launch(void* const* d_in, const int* in_sizes, int n_in,
                              void* d_out, int out_size) {
    const float* twist0 = (const float*)d_in[0];
    const float* x0     = (const float*)d_in[1];
    const float* x1     = (const float*)d_in[2];
    const float* invD0  = (const float*)d_in[3];
    const float* invD1  = (const float*)d_in[4];
    const float* sigma0 = (const float*)d_in[5];
    const float* sigma1 = (const float*)d_in[6];
    const float* Kmat   = (const float*)d_in[7];
    float* out = (float*)d_out;

    initKernel<<<1, BB>>>(twist0);
    packKernel<<<BCN/4/256, 256>>>(x0, sigma0, x1, sigma1);
    for (int it = 0; it < 3; ++it) {
        dim3 grid(NN/2/256, BB);
        iterKernel<<<grid, 256>>>(invD0, invD1, Kmat);
        solveKernel<<<1, BB>>>(out, it == 2);
    }
}